// round 2
// baseline (speedup 1.0000x reference)
#include <cuda_runtime.h>
#include <cstdint>

#define IN_F    128
#define OUT_F   64
#define NK      8      // spline basis count (NUM + K)
#define NF9     9      // 8 spline fields + silu field (x_lin split out)
#define TM      128    // rows per CTA
#define CI      4      // features per chunk
#define THREADS 256
#define XKC     16     // K-chunk for x_lin kernel

typedef unsigned long long u64;

// Prepped z-weights: [i][f][o], f 0..7 = coef*scale_sp*mask, f=8 = scale_base*mask
__device__ __align__(16) float g_wt[IN_F * NF9 * OUT_F];

__global__ void prep_kernel(const float* __restrict__ coef,
                            const float* __restrict__ scale_base,
                            const float* __restrict__ scale_sp,
                            const float* __restrict__ mask) {
    int idx = blockIdx.x * blockDim.x + threadIdx.x;
    if (idx >= IN_F * NF9 * OUT_F) return;
    int o = idx % OUT_F;
    int f = (idx / OUT_F) % NF9;
    int i = idx / (OUT_F * NF9);
    float v;
    if (f < NK) v = coef[(i * OUT_F + o) * NK + f] * scale_sp[i * OUT_F + o] * mask[i * OUT_F + o];
    else        v = scale_base[i * OUT_F + o] * mask[i * OUT_F + o];
    g_wt[idx] = v;
}

__device__ __forceinline__ u64 pk2(float v) {
    unsigned r = __float_as_uint(v);
    u64 d;
    asm("mov.b64 %0, {%1, %2};" : "=l"(d) : "r"(r), "r"(r));
    return d;
}
__device__ __forceinline__ void upk2(u64 v, float& lo, float& hi) {
    unsigned a, b;
    asm("mov.b64 {%0, %1}, %2;" : "=r"(a), "=r"(b) : "l"(v));
    lo = __uint_as_float(a);
    hi = __uint_as_float(b);
}
__device__ __forceinline__ u64 fma2(u64 a, u64 b, u64 c) {
    u64 d;
    asm("fma.rn.f32x2 %0, %1, %2, %3;" : "=l"(d) : "l"(a), "l"(b), "l"(c));
    return d;
}

// ---------------------------------------------------------------------------
// z kernel: z[n][o] = sum_i sum_f sS(n,i,f) * wt[i][f][o], then row-normalize.
// sS scalars stored DUPLICATED (u64) in smem -> fma2(row_scalar_dup, col_pair).
// ---------------------------------------------------------------------------
__global__ __launch_bounds__(THREADS, 3)
void enc_z_kernel(const float* __restrict__ x,
                  const float* __restrict__ grid,
                  float* __restrict__ zout,
                  int N) {
    __shared__ __align__(16) u64   sS[CI][NF9][TM];          // 36 KB (duplicated scalars)
    __shared__ __align__(16) float sW[CI * NF9 * OUT_F];     // 9 KB

    const int t    = threadIdx.x;
    const int cg   = t & 15;        // col group: cols cg*4 .. cg*4+3
    const int rg   = t >> 4;        // row group: rows rg*8 .. rg*8+7
    const int row0 = rg * 8;
    const int n0   = blockIdx.x * TM;

    const float g0   = grid[0];
    const float invh = 1.0f / (grid[1] - grid[0]);

    // acc[r][c]: r = row within 8-row group, c = col-pair (lanes = 2 cols)
    u64 acc[8][2];
#pragma unroll
    for (int r = 0; r < 8; r++) { acc[r][0] = 0ULL; acc[r][1] = 0ULL; }

    const int prow  = t >> 1;
    const int ibase = (t & 1) * 2;
    const int gn    = (n0 + prow < N) ? (n0 + prow) : (N - 1);
    const float* xrow = x + (size_t)gn * IN_F;

#pragma unroll 1
    for (int i0 = 0; i0 < IN_F; i0 += CI) {
        // stage weight fields for this chunk
        {
            const float4* src = (const float4*)(g_wt + i0 * (NF9 * OUT_F));
            float4* dst = (float4*)sW;
            for (int p = t; p < (CI * NF9 * OUT_F) / 4; p += THREADS)
                dst[p] = src[p];
        }

        // per-(row, feature) scalar prep -> duplicated u64
        float2 xv = *(const float2*)(xrow + i0 + ibase);
#pragma unroll
        for (int e = 0; e < 2; e++) {
            float a = e ? xv.y : xv.x;
            float s = a / (1.0f + __expf(-a));          // silu
            float tt = (a - g0) * invh;
            float mf = floorf(tt);
            float u  = tt - mf;
            float w0 = 0.f, w1 = 0.f, w2 = 0.f, w3 = 0.f;
            int   m  = 100;
            if (tt >= 0.0f && mf <= 10.0f) {
                m = (int)mf;
                float u2 = u * u, u3 = u2 * u;
                float omu = 1.0f - u;
                w0 = (1.0f / 6.0f) * omu * omu * omu;
                w1 = (1.0f / 6.0f) * (3.0f * u3 - 6.0f * u2 + 4.0f);
                w2 = (1.0f / 6.0f) * (-3.0f * u3 + 3.0f * u2 + 3.0f * u + 1.0f);
                w3 = (1.0f / 6.0f) * u3;
            }
            int ii = ibase + e;
#pragma unroll
            for (int j = 0; j < 8; j++) {
                int r = j - m + 3;
                float w = (r == 0) ? w0 : (r == 1) ? w1 : (r == 2) ? w2 : (r == 3) ? w3 : 0.0f;
                sS[ii][j][prow] = pk2(w);
            }
            sS[ii][8][prow] = pk2(s);
        }
        __syncthreads();

        // register-tiled accumulation: pure LDS + FMA2, no packing movs
#pragma unroll
        for (int ii = 0; ii < CI; ii++) {
#pragma unroll
            for (int f = 0; f < NF9; f++) {
                const u64* wp = (const u64*)(sW + (ii * NF9 + f) * OUT_F + cg * 4);
                u64 ww0 = wp[0], ww1 = wp[1];
                const u64* sp = &sS[ii][f][row0];
                u64 rr[8];
#pragma unroll
                for (int r = 0; r < 8; r++) rr[r] = sp[r];
#pragma unroll
                for (int r = 0; r < 8; r++) {
                    acc[r][0] = fma2(rr[r], ww0, acc[r][0]);
                    acc[r][1] = fma2(rr[r], ww1, acc[r][1]);
                }
            }
        }
        __syncthreads();
    }

    // epilogue: row-norm over 16 col-groups, scale, store
    float zf[8][4];
#pragma unroll
    for (int r = 0; r < 8; r++) {
        upk2(acc[r][0], zf[r][0], zf[r][1]);
        upk2(acc[r][1], zf[r][2], zf[r][3]);
    }

    float ssq[8];
#pragma unroll
    for (int r = 0; r < 8; r++)
        ssq[r] = zf[r][0] * zf[r][0] + zf[r][1] * zf[r][1]
               + zf[r][2] * zf[r][2] + zf[r][3] * zf[r][3];

#pragma unroll
    for (int msk = 1; msk < 16; msk <<= 1)
#pragma unroll
        for (int r = 0; r < 8; r++)
            ssq[r] += __shfl_xor_sync(0xffffffffu, ssq[r], msk);

#pragma unroll
    for (int r = 0; r < 8; r++) {
        int n = n0 + row0 + r;
        if (n < N) {
            float fac = 0.8f / fmaxf(sqrtf(ssq[r]), 1e-12f);
            float4 zv = make_float4(zf[r][0] * fac, zf[r][1] * fac,
                                    zf[r][2] * fac, zf[r][3] * fac);
            *(float4*)(zout + (size_t)n * OUT_F + cg * 4) = zv;
        }
    }
}

// ---------------------------------------------------------------------------
// x_lin kernel: x_lin = x @ W1^T   (M=N, K=128, N=64)
// ---------------------------------------------------------------------------
__global__ __launch_bounds__(THREADS, 3)
void xlin_kernel(const float* __restrict__ x,
                 const float* __restrict__ W1,
                 float* __restrict__ xlout,
                 int N) {
    __shared__ __align__(16) u64 sW1[IN_F][OUT_F / 2];   // [k][col-pair] 32 KB
    __shared__ __align__(16) u64 sX[XKC][TM];            // [k][row] duplicated, 16 KB

    const int t    = threadIdx.x;
    const int cg   = t & 15;
    const int rg   = t >> 4;
    const int row0 = rg * 8;
    const int n0   = blockIdx.x * TM;

    // stage W1: W1[o][k] -> sW1[k][o/2] halves (natural col-pair packing)
    for (int p = t; p < OUT_F * IN_F; p += THREADS) {
        int o = p >> 7;          // 0..63
        int k = p & 127;         // 0..127
        ((float*)&sW1[k][o >> 1])[o & 1] = W1[p];
    }

    u64 acc[8][2];
#pragma unroll
    for (int r = 0; r < 8; r++) { acc[r][0] = 0ULL; acc[r][1] = 0ULL; }

#pragma unroll 1
    for (int k0 = 0; k0 < IN_F; k0 += XKC) {
        // stage x chunk, duplicated u64, transposed [k][row]
        for (int p = t; p < TM * XKC / 4; p += THREADS) {
            int r  = p >> 2;
            int c4 = (p & 3) * 4;
            int gn = (n0 + r < N) ? (n0 + r) : (N - 1);
            float4 v = *(const float4*)(x + (size_t)gn * IN_F + k0 + c4);
            sX[c4 + 0][r] = pk2(v.x);
            sX[c4 + 1][r] = pk2(v.y);
            sX[c4 + 2][r] = pk2(v.z);
            sX[c4 + 3][r] = pk2(v.w);
        }
        __syncthreads();

#pragma unroll
        for (int k = 0; k < XKC; k++) {
            const u64* wp = &sW1[k0 + k][cg * 2];
            u64 ww0 = wp[0], ww1 = wp[1];
            const u64* sp = &sX[k][row0];
            u64 rr[8];
#pragma unroll
            for (int r = 0; r < 8; r++) rr[r] = sp[r];
#pragma unroll
            for (int r = 0; r < 8; r++) {
                acc[r][0] = fma2(rr[r], ww0, acc[r][0]);
                acc[r][1] = fma2(rr[r], ww1, acc[r][1]);
            }
        }
        __syncthreads();
    }

#pragma unroll
    for (int r = 0; r < 8; r++) {
        int n = n0 + row0 + r;
        if (n < N) {
            float a0, a1, a2, a3;
            upk2(acc[r][0], a0, a1);
            upk2(acc[r][1], a2, a3);
            *(float4*)(xlout + (size_t)n * OUT_F + cg * 4) = make_float4(a0, a1, a2, a3);
        }
    }
}

extern "C" void kernel_launch(void* const* d_in, const int* in_sizes, int n_in,
                              void* d_out, int out_size) {
    const float* x          = (const float*)d_in[0];
    const float* W1         = (const float*)d_in[1];
    const float* grid       = (const float*)d_in[2];
    const float* coef       = (const float*)d_in[3];
    const float* scale_base = (const float*)d_in[4];
    const float* scale_sp   = (const float*)d_in[5];
    const float* mask       = (const float*)d_in[6];
    // d_in[7] = edge_index: unused by the reference computation

    const int N = in_sizes[0] / IN_F;
    float* out   = (float*)d_out;
    float* zout  = out;                       // z first
    float* xlout = out + (size_t)N * OUT_F;   // then x_lin

    prep_kernel<<<(IN_F * NF9 * OUT_F + 255) / 256, 256>>>(coef, scale_base, scale_sp, mask);
    enc_z_kernel<<<(N + TM - 1) / TM, THREADS>>>(x, grid, zout, N);
    xlin_kernel<<<(N + TM - 1) / TM, THREADS>>>(x, W1, xlout, N);
}

// round 4
// speedup vs baseline: 1.1909x; 1.1909x over previous
#include <cuda_runtime.h>
#include <cuda_bf16.h>
#include <cstdint>

// 20 K-chunks of 64: 16 spline (8 feats x 8 basis), 2 silu, 2 raw-x (x_lin)
#define NCHUNK 20
#define TMR    128          // rows per CTA
#define THREADS 512

// B weights pre-baked in mma.sync B-fragment layout:
// g_Bf[c][kt][nt][lane] = uint4(b0_hi, b1_hi, b0_lo, b1_lo)
__device__ __align__(16) uint4 g_Bf[NCHUNK * 4 * 8 * 32];

// ---------------- helpers ----------------
__device__ __forceinline__ uint32_t smem_u32(const void* p) {
    uint32_t a;
    asm("{ .reg .u64 t; cvta.to.shared.u64 t, %1; cvt.u32.u64 %0, t; }" : "=r"(a) : "l"(p));
    return a;
}

#define LDM_X4(r0, r1, r2, r3, addr) \
    asm volatile("ldmatrix.sync.aligned.m8n8.x4.shared.b16 {%0,%1,%2,%3}, [%4];" \
                 : "=r"(r0), "=r"(r1), "=r"(r2), "=r"(r3) : "r"(addr))

#define MMA16816(c, a0, a1, a2, a3, b0, b1) \
    asm volatile("mma.sync.aligned.m16n8k16.row.col.f32.bf16.bf16.f32 " \
                 "{%0,%1,%2,%3}, {%4,%5,%6,%7}, {%8,%9}, {%0,%1,%2,%3};" \
                 : "+f"((c)[0]), "+f"((c)[1]), "+f"((c)[2]), "+f"((c)[3]) \
                 : "r"(a0), "r"(a1), "r"(a2), "r"(a3), "r"(b0), "r"(b1))

__device__ __forceinline__ void bsplit(float v, unsigned short& h, unsigned short& l) {
    __nv_bfloat16 bh = __float2bfloat16(v);
    h = __bfloat16_as_ushort(bh);
    l = __bfloat16_as_ushort(__float2bfloat16(v - __bfloat162float(bh)));
}

// weight value for (chunk c, local k 0..63, out col n)
__device__ __forceinline__ float wval(int c, int k, int n,
                                      const float* W1, const float* coef,
                                      const float* sb, const float* sp,
                                      const float* mask) {
    if (c < 16) {
        int i = c * 8 + (k >> 3), j = k & 7, io = i * 64 + n;
        return coef[io * 8 + j] * sp[io] * mask[io];
    }
    if (c < 18) {
        int io = ((c - 16) * 64 + k) * 64 + n;
        return sb[io] * mask[io];
    }
    return W1[n * 128 + (c - 18) * 64 + k];
}

// ---------------- B prep: bake fragments ----------------
__global__ void prepB_kernel(const float* __restrict__ W1, const float* __restrict__ coef,
                             const float* __restrict__ sb, const float* __restrict__ sp,
                             const float* __restrict__ mask) {
    int idx = blockIdx.x * blockDim.x + threadIdx.x;
    if (idx >= NCHUNK * 4 * 8 * 32) return;
    int lane = idx & 31, nt = (idx >> 5) & 7, kt = (idx >> 8) & 3, c = idx >> 10;
    int n  = nt * 8 + (lane >> 2);
    int k0 = kt * 16 + (lane & 3) * 2;
    float v00 = wval(c, k0,     n, W1, coef, sb, sp, mask);
    float v01 = wval(c, k0 + 1, n, W1, coef, sb, sp, mask);
    float v10 = wval(c, k0 + 8, n, W1, coef, sb, sp, mask);
    float v11 = wval(c, k0 + 9, n, W1, coef, sb, sp, mask);
    unsigned short h00, l00, h01, l01, h10, l10, h11, l11;
    bsplit(v00, h00, l00); bsplit(v01, h01, l01);
    bsplit(v10, h10, l10); bsplit(v11, h11, l11);
    uint4 r;
    r.x = (unsigned)h00 | ((unsigned)h01 << 16);   // b0 hi
    r.y = (unsigned)h10 | ((unsigned)h11 << 16);   // b1 hi
    r.z = (unsigned)l00 | ((unsigned)l01 << 16);   // b0 lo
    r.w = (unsigned)l10 | ((unsigned)l11 << 16);   // b1 lo
    g_Bf[idx] = r;
}

// ---------------- main kernel ----------------
// smem: sA_hi[128][72]bf16 (144B pitch) | sA_lo | sB[4][8][32]uint4 | sX[128][132]f32
#define OF_SA_H 0
#define OF_SA_L 18432
#define OF_SB   36864
#define OF_SX   53248
#define SMEM_TOTAL (53248 + 128 * 132 * 4)

__global__ __launch_bounds__(THREADS, 1)
void enc_mma_kernel(const float* __restrict__ x, const float* __restrict__ gridp,
                    float* __restrict__ zout, float* __restrict__ xlout, int N) {
    extern __shared__ char sm[];
    char*  sAh = sm + OF_SA_H;
    char*  sAl = sm + OF_SA_L;
    uint4* sB  = (uint4*)(sm + OF_SB);
    float* sX  = (float*)(sm + OF_SX);

    const int t    = threadIdx.x;
    const int wid  = t >> 5, lane = t & 31;
    const int wr   = wid & 7;        // row tile (16 rows)
    const int wc   = wid >> 3;       // col tile (32 cols)
    const int n0   = blockIdx.x * TMR;

    const float g0   = gridp[0];
    const float invh = 1.0f / (gridp[1] - gridp[0]);

    // load x tile (coalesced float4), clamp rows
    for (int p = t; p < TMR * 32; p += THREADS) {
        int row = p >> 5, c4 = (p & 31) << 2;
        int gn = n0 + row; if (gn >= N) gn = N - 1;
        *(float4*)(sX + row * 132 + c4) = *(const float4*)(x + (size_t)gn * 128 + c4);
    }

    float accz[4][4], accx[4][4];
#pragma unroll
    for (int a = 0; a < 4; a++)
#pragma unroll
        for (int b = 0; b < 4; b++) { accz[a][b] = 0.f; accx[a][b] = 0.f; }

    // per-lane ldmatrix row address components (fixed across chunks)
    const int lrow = wr * 16 + (lane & 7) + ((lane >> 3) & 1) * 8;
    const uint32_t aAddrH = smem_u32(sAh) + lrow * 144 + ((lane >> 4) * 8) * 2;
    const uint32_t aAddrL = smem_u32(sAl) + lrow * 144 + ((lane >> 4) * 8) * 2;

    __syncthreads();

    for (int c = 0; c < NCHUNK; ++c) {
        // ---- stage B fragments (already in fragment layout) ----
        {
            const uint4* gB = g_Bf + (size_t)c * 1024;
            sB[t]       = gB[t];
            sB[t + 512] = gB[t + 512];
        }
        // ---- A prep ----
        if (c < 16) {
            const int i0 = c * 8;
            const int fl = t & 7;
#pragma unroll
            for (int e = 0; e < 2; ++e) {
                const int row = (t >> 3) + e * 64;
                float a  = sX[row * 132 + i0 + fl];
                float tt = (a - g0) * invh;
                float mf = floorf(tt);
                int m = 100;
                float w0 = 0.f, w1 = 0.f, w2 = 0.f, w3 = 0.f;
                if (tt >= 0.0f && mf <= 10.0f) {
                    m = (int)mf;
                    float u = tt - mf, u2 = u * u, u3 = u2 * u, omu = 1.0f - u;
                    w0 = (1.0f / 6.0f) * omu * omu * omu;
                    w1 = (1.0f / 6.0f) * (3.0f * u3 - 6.0f * u2 + 4.0f);
                    w2 = (1.0f / 6.0f) * (-3.0f * u3 + 3.0f * u2 + 3.0f * u + 1.0f);
                    w3 = (1.0f / 6.0f) * u3;
                }
                unsigned hq[4], lq[4];
#pragma unroll
                for (int jp = 0; jp < 4; ++jp) {
                    unsigned hh = 0, ll = 0;
#pragma unroll
                    for (int e2 = 0; e2 < 2; ++e2) {
                        int r = (jp * 2 + e2) - m + 3;
                        float v = (r == 0) ? w0 : (r == 1) ? w1 : (r == 2) ? w2 : (r == 3) ? w3 : 0.0f;
                        unsigned short hs, ls; bsplit(v, hs, ls);
                        hh |= (unsigned)hs << (e2 * 16);
                        ll |= (unsigned)ls << (e2 * 16);
                    }
                    hq[jp] = hh; lq[jp] = ll;
                }
                *(uint4*)(sAh + row * 144 + fl * 16) = make_uint4(hq[0], hq[1], hq[2], hq[3]);
                *(uint4*)(sAl + row * 144 + fl * 16) = make_uint4(lq[0], lq[1], lq[2], lq[3]);
            }
        } else {
            const bool dosilu = (c < 18);
            const int i0 = (c & 1) * 64;
            const int row = t >> 2;
            const int f0 = (t & 3) * 16;
            float vv[16];
#pragma unroll
            for (int q = 0; q < 4; ++q) {
                float4 v = *(const float4*)(sX + row * 132 + i0 + f0 + q * 4);
                vv[q * 4 + 0] = v.x; vv[q * 4 + 1] = v.y;
                vv[q * 4 + 2] = v.z; vv[q * 4 + 3] = v.w;
            }
            unsigned hq[8], lq[8];
#pragma unroll
            for (int e = 0; e < 16; ++e) {
                float a = vv[e];
                float v = dosilu ? (a / (1.0f + __expf(-a))) : a;
                unsigned short hs, ls; bsplit(v, hs, ls);
                if (e & 1) { hq[e >> 1] |= (unsigned)hs << 16; lq[e >> 1] |= (unsigned)ls << 16; }
                else       { hq[e >> 1]  = hs;                 lq[e >> 1]  = ls; }
            }
            *(uint4*)(sAh + row * 144 + f0 * 2)      = make_uint4(hq[0], hq[1], hq[2], hq[3]);
            *(uint4*)(sAh + row * 144 + f0 * 2 + 16) = make_uint4(hq[4], hq[5], hq[6], hq[7]);
            *(uint4*)(sAl + row * 144 + f0 * 2)      = make_uint4(lq[0], lq[1], lq[2], lq[3]);
            *(uint4*)(sAl + row * 144 + f0 * 2 + 16) = make_uint4(lq[4], lq[5], lq[6], lq[7]);
        }
        __syncthreads();

        // ---- consume: 4 k-tiles x 4 n-tiles x 3 mma ----
#pragma unroll
        for (int kt = 0; kt < 4; ++kt) {
            uint32_t ah0, ah1, ah2, ah3, al0, al1, al2, al3;
            LDM_X4(ah0, ah1, ah2, ah3, aAddrH + kt * 32);
            LDM_X4(al0, al1, al2, al3, aAddrL + kt * 32);
            if (c < 18) {
#pragma unroll
                for (int nt = 0; nt < 4; ++nt) {
                    uint4 B = sB[(kt * 8 + wc * 4 + nt) * 32 + lane];
                    MMA16816(accz[nt], ah0, ah1, ah2, ah3, B.x, B.y);
                    MMA16816(accz[nt], ah0, ah1, ah2, ah3, B.z, B.w);
                    MMA16816(accz[nt], al0, al1, al2, al3, B.x, B.y);
                }
            } else {
#pragma unroll
                for (int nt = 0; nt < 4; ++nt) {
                    uint4 B = sB[(kt * 8 + wc * 4 + nt) * 32 + lane];
                    MMA16816(accx[nt], ah0, ah1, ah2, ah3, B.x, B.y);
                    MMA16816(accx[nt], ah0, ah1, ah2, ah3, B.z, B.w);
                    MMA16816(accx[nt], al0, al1, al2, al3, B.x, B.y);
                }
            }
        }
        __syncthreads();
    }

    // ---- epilogue: row norms across the 2 col tiles via smem ----
    float p0 = 0.f, p1 = 0.f;
#pragma unroll
    for (int nt = 0; nt < 4; ++nt) {
        p0 += accz[nt][0] * accz[nt][0] + accz[nt][1] * accz[nt][1];
        p1 += accz[nt][2] * accz[nt][2] + accz[nt][3] * accz[nt][3];
    }
    p0 += __shfl_xor_sync(0xffffffffu, p0, 1);
    p0 += __shfl_xor_sync(0xffffffffu, p0, 2);
    p1 += __shfl_xor_sync(0xffffffffu, p1, 1);
    p1 += __shfl_xor_sync(0xffffffffu, p1, 2);

    float* spart = sX;   // reuse: [coltile][row]
    const int r0 = wr * 16 + (lane >> 2), r1 = r0 + 8;
    if ((lane & 3) == 0) {
        spart[wc * 128 + r0] = p0;
        spart[wc * 128 + r1] = p1;
    }
    __syncthreads();

    const float fac0 = 0.8f / fmaxf(sqrtf(spart[r0] + spart[128 + r0]), 1e-12f);
    const float fac1 = 0.8f / fmaxf(sqrtf(spart[r1] + spart[128 + r1]), 1e-12f);

    const bool ok0 = (n0 + r0 < N), ok1 = (n0 + r1 < N);
#pragma unroll
    for (int nt = 0; nt < 4; ++nt) {
        int n = wc * 32 + nt * 8 + (lane & 3) * 2;
        if (ok0) {
            *(float2*)(zout  + (size_t)(n0 + r0) * 64 + n) = make_float2(accz[nt][0] * fac0, accz[nt][1] * fac0);
            *(float2*)(xlout + (size_t)(n0 + r0) * 64 + n) = make_float2(accx[nt][0], accx[nt][1]);
        }
        if (ok1) {
            *(float2*)(zout  + (size_t)(n0 + r1) * 64 + n) = make_float2(accz[nt][2] * fac1, accz[nt][3] * fac1);
            *(float2*)(xlout + (size_t)(n0 + r1) * 64 + n) = make_float2(accx[nt][2], accx[nt][3]);
        }
    }
}

extern "C" void kernel_launch(void* const* d_in, const int* in_sizes, int n_in,
                              void* d_out, int out_size) {
    const float* x          = (const float*)d_in[0];
    const float* W1         = (const float*)d_in[1];
    const float* grid       = (const float*)d_in[2];
    const float* coef       = (const float*)d_in[3];
    const float* scale_base = (const float*)d_in[4];
    const float* scale_sp   = (const float*)d_in[5];
    const float* mask       = (const float*)d_in[6];
    // d_in[7] = edge_index: unused by the reference computation

    const int N = in_sizes[0] / 128;
    float* out   = (float*)d_out;
    float* zout  = out;
    float* xlout = out + (size_t)N * 64;

    static int cfg = 0;
    if (!cfg) {
        cudaFuncSetAttribute(enc_mma_kernel, cudaFuncAttributeMaxDynamicSharedMemorySize, SMEM_TOTAL);
        cfg = 1;
    }

    prepB_kernel<<<(NCHUNK * 4 * 8 * 32 + 255) / 256, 256>>>(W1, coef, scale_base, scale_sp, mask);
    enc_mma_kernel<<<(N + TMR - 1) / TMR, THREADS, SMEM_TOTAL>>>(x, grid, zout, xlout, N);
}

// round 5
// speedup vs baseline: 1.1916x; 1.0006x over previous
#include <cuda_runtime.h>
#include <cuda_bf16.h>
#include <cstdint>

// 20 K-chunks of 64: 16 spline (8 feats x 8 basis), 2 silu, 2 raw-x (x_lin)
#define NCHUNK 20
#define TMR    128          // rows per CTA
#define THREADS 512

// B weights pre-baked in mma.sync B-fragment layout:
// g_Bf[c][kt][nt][lane] = uint4(b0_hi, b1_hi, b0_lo, b1_lo)
__device__ __align__(16) uint4 g_Bf[NCHUNK * 4 * 8 * 32];

// ---------------- helpers ----------------
__device__ __forceinline__ uint32_t smem_u32(const void* p) {
    uint32_t a;
    asm("{ .reg .u64 t; cvta.to.shared.u64 t, %1; cvt.u32.u64 %0, t; }" : "=r"(a) : "l"(p));
    return a;
}

#define LDM_X4(r0, r1, r2, r3, addr) \
    asm volatile("ldmatrix.sync.aligned.m8n8.x4.shared.b16 {%0,%1,%2,%3}, [%4];" \
                 : "=r"(r0), "=r"(r1), "=r"(r2), "=r"(r3) : "r"(addr))

#define MMA16816(c, a0, a1, a2, a3, b0, b1) \
    asm volatile("mma.sync.aligned.m16n8k16.row.col.f32.bf16.bf16.f32 " \
                 "{%0,%1,%2,%3}, {%4,%5,%6,%7}, {%8,%9}, {%0,%1,%2,%3};" \
                 : "+f"((c)[0]), "+f"((c)[1]), "+f"((c)[2]), "+f"((c)[3]) \
                 : "r"(a0), "r"(a1), "r"(a2), "r"(a3), "r"(b0), "r"(b1))

__device__ __forceinline__ void bsplit(float v, unsigned short& h, unsigned short& l) {
    __nv_bfloat16 bh = __float2bfloat16(v);
    h = __bfloat16_as_ushort(bh);
    l = __bfloat16_as_ushort(__float2bfloat16(v - __bfloat162float(bh)));
}

// weight value for (chunk c, local k 0..63, out col n)
__device__ __forceinline__ float wval(int c, int k, int n,
                                      const float* W1, const float* coef,
                                      const float* sb, const float* sp,
                                      const float* mask) {
    if (c < 16) {
        int i = c * 8 + (k >> 3), j = k & 7, io = i * 64 + n;
        return coef[io * 8 + j] * sp[io] * mask[io];
    }
    if (c < 18) {
        int io = ((c - 16) * 64 + k) * 64 + n;
        return sb[io] * mask[io];
    }
    return W1[n * 128 + (c - 18) * 64 + k];
}

// ---------------- B prep: bake fragments ----------------
__global__ void prepB_kernel(const float* __restrict__ W1, const float* __restrict__ coef,
                             const float* __restrict__ sb, const float* __restrict__ sp,
                             const float* __restrict__ mask) {
    int idx = blockIdx.x * blockDim.x + threadIdx.x;
    if (idx >= NCHUNK * 4 * 8 * 32) return;
    int lane = idx & 31, nt = (idx >> 5) & 7, kt = (idx >> 8) & 3, c = idx >> 10;
    int n  = nt * 8 + (lane >> 2);
    int k0 = kt * 16 + (lane & 3) * 2;
    float v00 = wval(c, k0,     n, W1, coef, sb, sp, mask);
    float v01 = wval(c, k0 + 1, n, W1, coef, sb, sp, mask);
    float v10 = wval(c, k0 + 8, n, W1, coef, sb, sp, mask);
    float v11 = wval(c, k0 + 9, n, W1, coef, sb, sp, mask);
    unsigned short h00, l00, h01, l01, h10, l10, h11, l11;
    bsplit(v00, h00, l00); bsplit(v01, h01, l01);
    bsplit(v10, h10, l10); bsplit(v11, h11, l11);
    uint4 r;
    r.x = (unsigned)h00 | ((unsigned)h01 << 16);   // b0 hi
    r.y = (unsigned)h10 | ((unsigned)h11 << 16);   // b1 hi
    r.z = (unsigned)l00 | ((unsigned)l01 << 16);   // b0 lo
    r.w = (unsigned)l10 | ((unsigned)l11 << 16);   // b1 lo
    g_Bf[idx] = r;
}

// ---------------- main kernel ----------------
// smem: sA_hi[128][72]bf16 (144B pitch) | sA_lo | sB[4][8][32]uint4 | sX[128][132]f32
#define OF_SA_H 0
#define OF_SA_L 18432
#define OF_SB   36864
#define OF_SX   53248
#define SMEM_TOTAL (53248 + 128 * 132 * 4)

__global__ __launch_bounds__(THREADS, 1)
void enc_mma_kernel(const float* __restrict__ x, const float* __restrict__ gridp,
                    float* __restrict__ zout, float* __restrict__ xlout, int N) {
    extern __shared__ char sm[];
    char*  sAh = sm + OF_SA_H;
    char*  sAl = sm + OF_SA_L;
    uint4* sB  = (uint4*)(sm + OF_SB);
    float* sX  = (float*)(sm + OF_SX);

    const int t    = threadIdx.x;
    const int wid  = t >> 5, lane = t & 31;
    const int wr   = wid & 7;        // row tile (16 rows)
    const int wc   = wid >> 3;       // col tile (32 cols)
    const int n0   = blockIdx.x * TMR;

    const float g0   = gridp[0];
    const float invh = 1.0f / (gridp[1] - gridp[0]);

    // load x tile (coalesced float4), clamp rows
    for (int p = t; p < TMR * 32; p += THREADS) {
        int row = p >> 5, c4 = (p & 31) << 2;
        int gn = n0 + row; if (gn >= N) gn = N - 1;
        *(float4*)(sX + row * 132 + c4) = *(const float4*)(x + (size_t)gn * 128 + c4);
    }

    float accz[4][4], accx[4][4];
#pragma unroll
    for (int a = 0; a < 4; a++)
#pragma unroll
        for (int b = 0; b < 4; b++) { accz[a][b] = 0.f; accx[a][b] = 0.f; }

    // per-lane ldmatrix row address components (fixed across chunks)
    const int lrow = wr * 16 + (lane & 7) + ((lane >> 3) & 1) * 8;
    const uint32_t aAddrH = smem_u32(sAh) + lrow * 144 + ((lane >> 4) * 8) * 2;
    const uint32_t aAddrL = smem_u32(sAl) + lrow * 144 + ((lane >> 4) * 8) * 2;

    __syncthreads();

    for (int c = 0; c < NCHUNK; ++c) {
        // ---- stage B fragments (already in fragment layout) ----
        {
            const uint4* gB = g_Bf + (size_t)c * 1024;
            sB[t]       = gB[t];
            sB[t + 512] = gB[t + 512];
        }
        // ---- A prep ----
        if (c < 16) {
            const int i0 = c * 8;
            const int fl = t & 7;
#pragma unroll
            for (int e = 0; e < 2; ++e) {
                const int row = (t >> 3) + e * 64;
                float a  = sX[row * 132 + i0 + fl];
                float tt = (a - g0) * invh;
                float mf = floorf(tt);
                int m = 100;
                float w0 = 0.f, w1 = 0.f, w2 = 0.f, w3 = 0.f;
                if (tt >= 0.0f && mf <= 10.0f) {
                    m = (int)mf;
                    float u = tt - mf, u2 = u * u, u3 = u2 * u, omu = 1.0f - u;
                    w0 = (1.0f / 6.0f) * omu * omu * omu;
                    w1 = (1.0f / 6.0f) * (3.0f * u3 - 6.0f * u2 + 4.0f);
                    w2 = (1.0f / 6.0f) * (-3.0f * u3 + 3.0f * u2 + 3.0f * u + 1.0f);
                    w3 = (1.0f / 6.0f) * u3;
                }
                unsigned hq[4], lq[4];
#pragma unroll
                for (int jp = 0; jp < 4; ++jp) {
                    unsigned hh = 0, ll = 0;
#pragma unroll
                    for (int e2 = 0; e2 < 2; ++e2) {
                        int r = (jp * 2 + e2) - m + 3;
                        float v = (r == 0) ? w0 : (r == 1) ? w1 : (r == 2) ? w2 : (r == 3) ? w3 : 0.0f;
                        unsigned short hs, ls; bsplit(v, hs, ls);
                        hh |= (unsigned)hs << (e2 * 16);
                        ll |= (unsigned)ls << (e2 * 16);
                    }
                    hq[jp] = hh; lq[jp] = ll;
                }
                *(uint4*)(sAh + row * 144 + fl * 16) = make_uint4(hq[0], hq[1], hq[2], hq[3]);
                *(uint4*)(sAl + row * 144 + fl * 16) = make_uint4(lq[0], lq[1], lq[2], lq[3]);
            }
        } else {
            const bool dosilu = (c < 18);
            const int i0 = (c & 1) * 64;
            const int row = t >> 2;
            const int f0 = (t & 3) * 16;
            float vv[16];
#pragma unroll
            for (int q = 0; q < 4; ++q) {
                float4 v = *(const float4*)(sX + row * 132 + i0 + f0 + q * 4);
                vv[q * 4 + 0] = v.x; vv[q * 4 + 1] = v.y;
                vv[q * 4 + 2] = v.z; vv[q * 4 + 3] = v.w;
            }
            unsigned hq[8], lq[8];
#pragma unroll
            for (int e = 0; e < 16; ++e) {
                float a = vv[e];
                float v = dosilu ? (a / (1.0f + __expf(-a))) : a;
                unsigned short hs, ls; bsplit(v, hs, ls);
                if (e & 1) { hq[e >> 1] |= (unsigned)hs << 16; lq[e >> 1] |= (unsigned)ls << 16; }
                else       { hq[e >> 1]  = hs;                 lq[e >> 1]  = ls; }
            }
            *(uint4*)(sAh + row * 144 + f0 * 2)      = make_uint4(hq[0], hq[1], hq[2], hq[3]);
            *(uint4*)(sAh + row * 144 + f0 * 2 + 16) = make_uint4(hq[4], hq[5], hq[6], hq[7]);
            *(uint4*)(sAl + row * 144 + f0 * 2)      = make_uint4(lq[0], lq[1], lq[2], lq[3]);
            *(uint4*)(sAl + row * 144 + f0 * 2 + 16) = make_uint4(lq[4], lq[5], lq[6], lq[7]);
        }
        __syncthreads();

        // ---- consume: 4 k-tiles x 4 n-tiles x 3 mma ----
#pragma unroll
        for (int kt = 0; kt < 4; ++kt) {
            uint32_t ah0, ah1, ah2, ah3, al0, al1, al2, al3;
            LDM_X4(ah0, ah1, ah2, ah3, aAddrH + kt * 32);
            LDM_X4(al0, al1, al2, al3, aAddrL + kt * 32);
            if (c < 18) {
#pragma unroll
                for (int nt = 0; nt < 4; ++nt) {
                    uint4 B = sB[(kt * 8 + wc * 4 + nt) * 32 + lane];
                    MMA16816(accz[nt], ah0, ah1, ah2, ah3, B.x, B.y);
                    MMA16816(accz[nt], ah0, ah1, ah2, ah3, B.z, B.w);
                    MMA16816(accz[nt], al0, al1, al2, al3, B.x, B.y);
                }
            } else {
#pragma unroll
                for (int nt = 0; nt < 4; ++nt) {
                    uint4 B = sB[(kt * 8 + wc * 4 + nt) * 32 + lane];
                    MMA16816(accx[nt], ah0, ah1, ah2, ah3, B.x, B.y);
                    MMA16816(accx[nt], ah0, ah1, ah2, ah3, B.z, B.w);
                    MMA16816(accx[nt], al0, al1, al2, al3, B.x, B.y);
                }
            }
        }
        __syncthreads();
    }

    // ---- epilogue: row norms across the 2 col tiles via smem ----
    float p0 = 0.f, p1 = 0.f;
#pragma unroll
    for (int nt = 0; nt < 4; ++nt) {
        p0 += accz[nt][0] * accz[nt][0] + accz[nt][1] * accz[nt][1];
        p1 += accz[nt][2] * accz[nt][2] + accz[nt][3] * accz[nt][3];
    }
    p0 += __shfl_xor_sync(0xffffffffu, p0, 1);
    p0 += __shfl_xor_sync(0xffffffffu, p0, 2);
    p1 += __shfl_xor_sync(0xffffffffu, p1, 1);
    p1 += __shfl_xor_sync(0xffffffffu, p1, 2);

    float* spart = sX;   // reuse: [coltile][row]
    const int r0 = wr * 16 + (lane >> 2), r1 = r0 + 8;
    if ((lane & 3) == 0) {
        spart[wc * 128 + r0] = p0;
        spart[wc * 128 + r1] = p1;
    }
    __syncthreads();

    const float fac0 = 0.8f / fmaxf(sqrtf(spart[r0] + spart[128 + r0]), 1e-12f);
    const float fac1 = 0.8f / fmaxf(sqrtf(spart[r1] + spart[128 + r1]), 1e-12f);

    const bool ok0 = (n0 + r0 < N), ok1 = (n0 + r1 < N);
#pragma unroll
    for (int nt = 0; nt < 4; ++nt) {
        int n = wc * 32 + nt * 8 + (lane & 3) * 2;
        if (ok0) {
            *(float2*)(zout  + (size_t)(n0 + r0) * 64 + n) = make_float2(accz[nt][0] * fac0, accz[nt][1] * fac0);
            *(float2*)(xlout + (size_t)(n0 + r0) * 64 + n) = make_float2(accx[nt][0], accx[nt][1]);
        }
        if (ok1) {
            *(float2*)(zout  + (size_t)(n0 + r1) * 64 + n) = make_float2(accz[nt][2] * fac1, accz[nt][3] * fac1);
            *(float2*)(xlout + (size_t)(n0 + r1) * 64 + n) = make_float2(accx[nt][2], accx[nt][3]);
        }
    }
}

extern "C" void kernel_launch(void* const* d_in, const int* in_sizes, int n_in,
                              void* d_out, int out_size) {
    const float* x          = (const float*)d_in[0];
    const float* W1         = (const float*)d_in[1];
    const float* grid       = (const float*)d_in[2];
    const float* coef       = (const float*)d_in[3];
    const float* scale_base = (const float*)d_in[4];
    const float* scale_sp   = (const float*)d_in[5];
    const float* mask       = (const float*)d_in[6];
    // d_in[7] = edge_index: unused by the reference computation

    const int N = in_sizes[0] / 128;
    float* out   = (float*)d_out;
    float* zout  = out;
    float* xlout = out + (size_t)N * 64;

    static int cfg = 0;
    if (!cfg) {
        cudaFuncSetAttribute(enc_mma_kernel, cudaFuncAttributeMaxDynamicSharedMemorySize, SMEM_TOTAL);
        cfg = 1;
    }

    prepB_kernel<<<(NCHUNK * 4 * 8 * 32 + 255) / 256, 256>>>(W1, coef, scale_base, scale_sp, mask);
    enc_mma_kernel<<<(N + TMR - 1) / TMR, THREADS, SMEM_TOTAL>>>(x, grid, zout, xlout, N);
}

// round 6
// speedup vs baseline: 2.5139x; 2.1096x over previous
#include <cuda_runtime.h>
#include <cuda_bf16.h>
#include <cstdint>

#define NCHUNK 20
#define TMR    128
#define THREADS 512
#define A_HL   18432            // bytes per A image (128 rows x 144B)
#define A_BUF  (2 * A_HL)       // hi + lo
#define OF_A   0
#define OF_B   (2 * A_BUF)                  // 73728
#define OF_X   (OF_B + 2 * 16384)           // 106496
#define SMEM_TOTAL (OF_X + 128 * 132 * 4)   // 174080

// B fragments: [c][kt][nt][lane] = uint4(b0_hi, b1_hi, b0_lo, b1_lo)
__device__ __align__(16) uint4 g_Bf[NCHUNK * 4 * 8 * 32];

__device__ __forceinline__ uint32_t smem_u32(const void* p) {
    uint32_t a;
    asm("{ .reg .u64 t; cvta.to.shared.u64 t, %1; cvt.u32.u64 %0, t; }" : "=r"(a) : "l"(p));
    return a;
}
#define LDM_X4(r0, r1, r2, r3, addr) \
    asm volatile("ldmatrix.sync.aligned.m8n8.x4.shared.b16 {%0,%1,%2,%3}, [%4];" \
                 : "=r"(r0), "=r"(r1), "=r"(r2), "=r"(r3) : "r"(addr))
#define MMA16816(c, a0, a1, a2, a3, b0, b1) \
    asm volatile("mma.sync.aligned.m16n8k16.row.col.f32.bf16.bf16.f32 " \
                 "{%0,%1,%2,%3}, {%4,%5,%6,%7}, {%8,%9}, {%0,%1,%2,%3};" \
                 : "+f"((c)[0]), "+f"((c)[1]), "+f"((c)[2]), "+f"((c)[3]) \
                 : "r"(a0), "r"(a1), "r"(a2), "r"(a3), "r"(b0), "r"(b1))

// pack (lo,hi) floats -> bf16x2 word (lo in low 16 bits)
__device__ __forceinline__ uint32_t pkbf2(float lo, float hi) {
    uint32_t d;
    asm("cvt.rn.bf16x2.f32 %0, %1, %2;" : "=r"(d) : "f"(hi), "f"(lo));
    return d;
}
__device__ __forceinline__ void bsplit(float v, unsigned short& h, unsigned short& l) {
    __nv_bfloat16 bh = __float2bfloat16(v);
    h = __bfloat16_as_ushort(bh);
    l = __bfloat16_as_ushort(__float2bfloat16(v - __bfloat162float(bh)));
}
__device__ __forceinline__ float wval(int c, int k, int n,
                                      const float* W1, const float* coef,
                                      const float* sb, const float* sp,
                                      const float* mask) {
    if (c < 16) {
        int i = c * 8 + (k >> 3), j = k & 7, io = i * 64 + n;
        return coef[io * 8 + j] * sp[io] * mask[io];
    }
    if (c < 18) {
        int io = ((c - 16) * 64 + k) * 64 + n;
        return sb[io] * mask[io];
    }
    return W1[n * 128 + (c - 18) * 64 + k];
}

__global__ void prepB_kernel(const float* __restrict__ W1, const float* __restrict__ coef,
                             const float* __restrict__ sb, const float* __restrict__ sp,
                             const float* __restrict__ mask) {
    int idx = blockIdx.x * blockDim.x + threadIdx.x;
    if (idx >= NCHUNK * 4 * 8 * 32) return;
    int lane = idx & 31, nt = (idx >> 5) & 7, kt = (idx >> 8) & 3, c = idx >> 10;
    int n  = nt * 8 + (lane >> 2);
    int k0 = kt * 16 + (lane & 3) * 2;
    float v00 = wval(c, k0,     n, W1, coef, sb, sp, mask);
    float v01 = wval(c, k0 + 1, n, W1, coef, sb, sp, mask);
    float v10 = wval(c, k0 + 8, n, W1, coef, sb, sp, mask);
    float v11 = wval(c, k0 + 9, n, W1, coef, sb, sp, mask);
    unsigned short h00, l00, h01, l01, h10, l10, h11, l11;
    bsplit(v00, h00, l00); bsplit(v01, h01, l01);
    bsplit(v10, h10, l10); bsplit(v11, h11, l11);
    uint4 r;
    r.x = (unsigned)h00 | ((unsigned)h01 << 16);
    r.y = (unsigned)h10 | ((unsigned)h11 << 16);
    r.z = (unsigned)l00 | ((unsigned)l01 << 16);
    r.w = (unsigned)l10 | ((unsigned)l11 << 16);
    g_Bf[idx] = r;
}

// ---- A-prep for chunk cc into buffer nb (all 512 threads) ----
__device__ __forceinline__ void prepA(int cc, int nb, int t, char* smA, const float* sX,
                                      float g0, float invh) {
    char* bAh = smA + nb * A_BUF;
    char* bAl = bAh + A_HL;
    if (cc < 16) {
        const int i0 = cc * 8, fl = t & 7;
#pragma unroll
        for (int e = 0; e < 2; ++e) {
            const int row = (t >> 3) + e * 64;
            float a  = sX[row * 132 + i0 + fl];
            float tt = (a - g0) * invh;
            float mf = floorf(tt);
            float u  = tt - mf;
            float w0, w1, w2, w3; int m;
            if (tt >= 0.0f && mf <= 10.0f) {
                m = (int)mf;
                float u2 = u * u, u3 = u2 * u, omu = 1.0f - u;
                w0 = (1.0f / 6.0f) * omu * omu * omu;
                w1 = (1.0f / 6.0f) * (3.0f * u3 - 6.0f * u2 + 4.0f);
                w2 = (1.0f / 6.0f) * (-3.0f * u3 + 3.0f * u2 + 3.0f * u + 1.0f);
                w3 = (1.0f / 6.0f) * u3;
            } else { m = 100; w0 = w1 = w2 = w3 = 0.f; }
            char* dH = bAh + row * 144 + fl * 16;
            char* dL = bAl + row * 144 + fl * 16;
            *(uint4*)dH = make_uint4(0, 0, 0, 0);
            *(uint4*)dL = make_uint4(0, 0, 0, 0);
            int j0 = (m - 3) & ~1, p = (m - 3) & 1;
            float a0 = p ? 0.f : w0, b0 = p ? w0 : w1;
            float a1 = p ? w1 : w2, b1 = p ? w2 : w3;
            uint32_t W0 = pkbf2(a0, b0), W1 = pkbf2(a1, b1), W2 = pkbf2(w3, 0.f);
            float r0l = a0 - __uint_as_float(W0 << 16);
            float r0h = b0 - __uint_as_float(W0 & 0xffff0000u);
            float r1l = a1 - __uint_as_float(W1 << 16);
            float r1h = b1 - __uint_as_float(W1 & 0xffff0000u);
            float r2l = w3 - __uint_as_float(W2 << 16);
            uint32_t L0 = pkbf2(r0l, r0h), L1 = pkbf2(r1l, r1h), L2 = pkbf2(r2l, 0.f);
            if ((unsigned)j0 <= 6u)       { *(uint32_t*)(dH + j0 * 2) = W0;       *(uint32_t*)(dL + j0 * 2) = L0; }
            if ((unsigned)(j0 + 2) <= 6u) { *(uint32_t*)(dH + (j0 + 2) * 2) = W1; *(uint32_t*)(dL + (j0 + 2) * 2) = L1; }
            if (p && (unsigned)(j0 + 4) <= 6u) { *(uint32_t*)(dH + (j0 + 4) * 2) = W2; *(uint32_t*)(dL + (j0 + 4) * 2) = L2; }
        }
    } else {
        const bool dosilu = (cc < 18);
        const int i0 = (cc & 1) * 64, row = t >> 2, f0 = (t & 3) * 16;
        float vv[16];
#pragma unroll
        for (int q = 0; q < 4; ++q) {
            float4 v = *(const float4*)(sX + row * 132 + i0 + f0 + q * 4);
            vv[q * 4 + 0] = v.x; vv[q * 4 + 1] = v.y; vv[q * 4 + 2] = v.z; vv[q * 4 + 3] = v.w;
        }
        uint32_t hq[8], lq[8];
#pragma unroll
        for (int q = 0; q < 8; ++q) {
            float pa = vv[2 * q], pb = vv[2 * q + 1];
            if (dosilu) {
                pa = pa / (1.0f + __expf(-pa));
                pb = pb / (1.0f + __expf(-pb));
            }
            hq[q] = pkbf2(pa, pb);
            float ra = pa - __uint_as_float(hq[q] << 16);
            float rb = pb - __uint_as_float(hq[q] & 0xffff0000u);
            lq[q] = pkbf2(ra, rb);
        }
        char* dH = bAh + row * 144 + f0 * 2;
        char* dL = bAl + row * 144 + f0 * 2;
        *(uint4*)(dH)      = make_uint4(hq[0], hq[1], hq[2], hq[3]);
        *(uint4*)(dH + 16) = make_uint4(hq[4], hq[5], hq[6], hq[7]);
        *(uint4*)(dL)      = make_uint4(lq[0], lq[1], lq[2], lq[3]);
        *(uint4*)(dL + 16) = make_uint4(lq[4], lq[5], lq[6], lq[7]);
    }
}

__global__ __launch_bounds__(THREADS, 1)
void enc_mma_kernel(const float* __restrict__ x, const float* __restrict__ gridp,
                    float* __restrict__ zout, float* __restrict__ xlout, int N) {
    extern __shared__ char sm[];
    char*  smA = sm + OF_A;
    uint4* sB  = (uint4*)(sm + OF_B);
    float* sX  = (float*)(sm + OF_X);

    const int t = threadIdx.x, wid = t >> 5, lane = t & 31;
    const int wr = wid & 7, wc = wid >> 3;
    const int n0 = blockIdx.x * TMR;

    const float g0   = gridp[0];
    const float invh = 1.0f / (gridp[1] - gridp[0]);

    for (int p = t; p < TMR * 32; p += THREADS) {
        int row = p >> 5, c4 = (p & 31) << 2;
        int gn = n0 + row; if (gn >= N) gn = N - 1;
        *(float4*)(sX + row * 132 + c4) = *(const float4*)(x + (size_t)gn * 128 + c4);
    }

    float accz[4][4], accx[4][4];
#pragma unroll
    for (int a = 0; a < 4; a++)
#pragma unroll
        for (int b = 0; b < 4; b++) { accz[a][b] = 0.f; accx[a][b] = 0.f; }

    const int lrow = wr * 16 + (lane & 7) + ((lane >> 3) & 1) * 8;
    const uint32_t aOff = smem_u32(smA) + lrow * 144 + ((lane >> 4) * 8) * 2;

    __syncthreads();   // sX ready (prepA reads it)

    // prologue: stage B(0), prep A(0) into buf 0
    sB[t]       = g_Bf[t];
    sB[t + 512] = g_Bf[t + 512];
    prepA(0, 0, t, smA, sX, g0, invh);
    __syncthreads();

    for (int c = 0; c < NCHUNK; ++c) {
        const int cb = c & 1, nb = cb ^ 1;
        const bool more = (c + 1 < NCHUNK);
        uint4 pb0, pb1;
        if (more) {
            pb0 = g_Bf[(c + 1) * 1024 + t];
            pb1 = g_Bf[(c + 1) * 1024 + t + 512];
        }
        // ---- consume chunk c ----
        const uint32_t aH = aOff + cb * A_BUF;
        const uint4* sBb = sB + cb * 1024;
#pragma unroll
        for (int kt = 0; kt < 4; ++kt) {
            uint32_t ah0, ah1, ah2, ah3, al0, al1, al2, al3;
            LDM_X4(ah0, ah1, ah2, ah3, aH + kt * 32);
            LDM_X4(al0, al1, al2, al3, aH + A_HL + kt * 32);
            if (c < 18) {
#pragma unroll
                for (int nt = 0; nt < 4; ++nt) {
                    uint4 B = sBb[(kt * 8 + wc * 4 + nt) * 32 + lane];
                    MMA16816(accz[nt], ah0, ah1, ah2, ah3, B.x, B.y);
                    MMA16816(accz[nt], ah0, ah1, ah2, ah3, B.z, B.w);
                    MMA16816(accz[nt], al0, al1, al2, al3, B.x, B.y);
                }
            } else {
#pragma unroll
                for (int nt = 0; nt < 4; ++nt) {
                    uint4 B = sBb[(kt * 8 + wc * 4 + nt) * 32 + lane];
                    MMA16816(accx[nt], ah0, ah1, ah2, ah3, B.x, B.y);
                    MMA16816(accx[nt], ah0, ah1, ah2, ah3, B.z, B.w);
                    MMA16816(accx[nt], al0, al1, al2, al3, B.x, B.y);
                }
            }
        }
        // ---- produce chunk c+1 ----
        if (more) {
            sB[nb * 1024 + t]       = pb0;
            sB[nb * 1024 + t + 512] = pb1;
            prepA(c + 1, nb, t, smA, sX, g0, invh);
        }
        __syncthreads();
    }

    // ---- epilogue (verified in R4) ----
    float p0 = 0.f, p1 = 0.f;
#pragma unroll
    for (int nt = 0; nt < 4; ++nt) {
        p0 += accz[nt][0] * accz[nt][0] + accz[nt][1] * accz[nt][1];
        p1 += accz[nt][2] * accz[nt][2] + accz[nt][3] * accz[nt][3];
    }
    p0 += __shfl_xor_sync(0xffffffffu, p0, 1);
    p0 += __shfl_xor_sync(0xffffffffu, p0, 2);
    p1 += __shfl_xor_sync(0xffffffffu, p1, 1);
    p1 += __shfl_xor_sync(0xffffffffu, p1, 2);

    float* spart = sX;
    const int r0 = wr * 16 + (lane >> 2), r1 = r0 + 8;
    if ((lane & 3) == 0) {
        spart[wc * 128 + r0] = p0;
        spart[wc * 128 + r1] = p1;
    }
    __syncthreads();

    const float fac0 = 0.8f / fmaxf(sqrtf(spart[r0] + spart[128 + r0]), 1e-12f);
    const float fac1 = 0.8f / fmaxf(sqrtf(spart[r1] + spart[128 + r1]), 1e-12f);
    const bool ok0 = (n0 + r0 < N), ok1 = (n0 + r1 < N);
#pragma unroll
    for (int nt = 0; nt < 4; ++nt) {
        int n = wc * 32 + nt * 8 + (lane & 3) * 2;
        if (ok0) {
            *(float2*)(zout  + (size_t)(n0 + r0) * 64 + n) = make_float2(accz[nt][0] * fac0, accz[nt][1] * fac0);
            *(float2*)(xlout + (size_t)(n0 + r0) * 64 + n) = make_float2(accx[nt][0], accx[nt][1]);
        }
        if (ok1) {
            *(float2*)(zout  + (size_t)(n0 + r1) * 64 + n) = make_float2(accz[nt][2] * fac1, accz[nt][3] * fac1);
            *(float2*)(xlout + (size_t)(n0 + r1) * 64 + n) = make_float2(accx[nt][2], accx[nt][3]);
        }
    }
}

extern "C" void kernel_launch(void* const* d_in, const int* in_sizes, int n_in,
                              void* d_out, int out_size) {
    const float* x          = (const float*)d_in[0];
    const float* W1         = (const float*)d_in[1];
    const float* grid       = (const float*)d_in[2];
    const float* coef       = (const float*)d_in[3];
    const float* scale_base = (const float*)d_in[4];
    const float* scale_sp   = (const float*)d_in[5];
    const float* mask       = (const float*)d_in[6];
    // d_in[7] = edge_index: unused by the reference

    const int N = in_sizes[0] / 128;
    float* out   = (float*)d_out;
    float* zout  = out;
    float* xlout = out + (size_t)N * 64;

    cudaFuncSetAttribute(enc_mma_kernel, cudaFuncAttributeMaxDynamicSharedMemorySize, SMEM_TOTAL);
    prepB_kernel<<<(NCHUNK * 4 * 8 * 32 + 255) / 256, 256>>>(W1, coef, scale_base, scale_sp, mask);
    enc_mma_kernel<<<(N + TMR - 1) / TMR, THREADS, SMEM_TOTAL>>>(x, grid, zout, xlout, N);
}

// round 7
// speedup vs baseline: 2.7446x; 1.0918x over previous
#include <cuda_runtime.h>
#include <cuda_bf16.h>
#include <cstdint>

#define NCHUNK 20
#define TMR    64
#define THREADS 256
#define A_HL   9216             // bytes per A image (64 rows x 144B)
#define A_BUF  (2 * A_HL)       // hi + lo
#define OF_A   0
#define OF_B   (2 * A_BUF)                  // 36864
#define OF_X   (OF_B + 2 * 16384)           // 69632
#define SMEM_TOTAL (OF_X + TMR * 132 * 4)   // 103424

// B fragments: [c][kt][nt][lane] = uint4(b0_hi, b1_hi, b0_lo, b1_lo)
__device__ __align__(16) uint4 g_Bf[NCHUNK * 4 * 8 * 32];

__device__ __forceinline__ uint32_t smem_u32(const void* p) {
    uint32_t a;
    asm("{ .reg .u64 t; cvta.to.shared.u64 t, %1; cvt.u32.u64 %0, t; }" : "=r"(a) : "l"(p));
    return a;
}
#define LDM_X4(r0, r1, r2, r3, addr) \
    asm volatile("ldmatrix.sync.aligned.m8n8.x4.shared.b16 {%0,%1,%2,%3}, [%4];" \
                 : "=r"(r0), "=r"(r1), "=r"(r2), "=r"(r3) : "r"(addr))
#define MMA16816(c, a0, a1, a2, a3, b0, b1) \
    asm volatile("mma.sync.aligned.m16n8k16.row.col.f32.bf16.bf16.f32 " \
                 "{%0,%1,%2,%3}, {%4,%5,%6,%7}, {%8,%9}, {%0,%1,%2,%3};" \
                 : "+f"((c)[0]), "+f"((c)[1]), "+f"((c)[2]), "+f"((c)[3]) \
                 : "r"(a0), "r"(a1), "r"(a2), "r"(a3), "r"(b0), "r"(b1))

__device__ __forceinline__ uint32_t pkbf2(float lo, float hi) {
    uint32_t d;
    asm("cvt.rn.bf16x2.f32 %0, %1, %2;" : "=r"(d) : "f"(hi), "f"(lo));
    return d;
}
__device__ __forceinline__ void bsplit(float v, unsigned short& h, unsigned short& l) {
    __nv_bfloat16 bh = __float2bfloat16(v);
    h = __bfloat16_as_ushort(bh);
    l = __bfloat16_as_ushort(__float2bfloat16(v - __bfloat162float(bh)));
}
__device__ __forceinline__ float wval(int c, int k, int n,
                                      const float* W1, const float* coef,
                                      const float* sb, const float* sp,
                                      const float* mask) {
    if (c < 16) {
        int i = c * 8 + (k >> 3), j = k & 7, io = i * 64 + n;
        return coef[io * 8 + j] * sp[io] * mask[io];
    }
    if (c < 18) {
        int io = ((c - 16) * 64 + k) * 64 + n;
        return sb[io] * mask[io];
    }
    return W1[n * 128 + (c - 18) * 64 + k];
}

__global__ void prepB_kernel(const float* __restrict__ W1, const float* __restrict__ coef,
                             const float* __restrict__ sb, const float* __restrict__ sp,
                             const float* __restrict__ mask) {
    int idx = blockIdx.x * blockDim.x + threadIdx.x;
    if (idx >= NCHUNK * 4 * 8 * 32) return;
    int lane = idx & 31, nt = (idx >> 5) & 7, kt = (idx >> 8) & 3, c = idx >> 10;
    int n  = nt * 8 + (lane >> 2);
    int k0 = kt * 16 + (lane & 3) * 2;
    float v00 = wval(c, k0,     n, W1, coef, sb, sp, mask);
    float v01 = wval(c, k0 + 1, n, W1, coef, sb, sp, mask);
    float v10 = wval(c, k0 + 8, n, W1, coef, sb, sp, mask);
    float v11 = wval(c, k0 + 9, n, W1, coef, sb, sp, mask);
    unsigned short h00, l00, h01, l01, h10, l10, h11, l11;
    bsplit(v00, h00, l00); bsplit(v01, h01, l01);
    bsplit(v10, h10, l10); bsplit(v11, h11, l11);
    uint4 r;
    r.x = (unsigned)h00 | ((unsigned)h01 << 16);
    r.y = (unsigned)h10 | ((unsigned)h11 << 16);
    r.z = (unsigned)l00 | ((unsigned)l01 << 16);
    r.w = (unsigned)l10 | ((unsigned)l11 << 16);
    g_Bf[idx] = r;
}

// ---- A-prep for chunk cc into buffer nb (all 256 threads, 64 rows) ----
__device__ __forceinline__ void prepA(int cc, int nb, int t, char* smA, const float* sX,
                                      float g0, float invh) {
    char* bAh = smA + nb * A_BUF;
    char* bAl = bAh + A_HL;
    if (cc < 16) {
        const int i0 = cc * 8, fl = t & 7;
#pragma unroll
        for (int e = 0; e < 2; ++e) {
            const int row = (t >> 3) + e * 32;
            float a  = sX[row * 132 + i0 + fl];
            float tt = (a - g0) * invh;
            float mf = floorf(tt);
            float u  = tt - mf;
            float w0, w1, w2, w3; int m;
            if (tt >= 0.0f && mf <= 10.0f) {
                m = (int)mf;
                float u2 = u * u, u3 = u2 * u, omu = 1.0f - u;
                w0 = (1.0f / 6.0f) * omu * omu * omu;
                w1 = (1.0f / 6.0f) * (3.0f * u3 - 6.0f * u2 + 4.0f);
                w2 = (1.0f / 6.0f) * (-3.0f * u3 + 3.0f * u2 + 3.0f * u + 1.0f);
                w3 = (1.0f / 6.0f) * u3;
            } else { m = 100; w0 = w1 = w2 = w3 = 0.f; }
            char* dH = bAh + row * 144 + fl * 16;
            char* dL = bAl + row * 144 + fl * 16;
            *(uint4*)dH = make_uint4(0, 0, 0, 0);
            *(uint4*)dL = make_uint4(0, 0, 0, 0);
            int j0 = (m - 3) & ~1, p = (m - 3) & 1;
            float a0 = p ? 0.f : w0, b0 = p ? w0 : w1;
            float a1 = p ? w1 : w2, b1 = p ? w2 : w3;
            uint32_t W0 = pkbf2(a0, b0), W1 = pkbf2(a1, b1), W2 = pkbf2(w3, 0.f);
            float r0l = a0 - __uint_as_float(W0 << 16);
            float r0h = b0 - __uint_as_float(W0 & 0xffff0000u);
            float r1l = a1 - __uint_as_float(W1 << 16);
            float r1h = b1 - __uint_as_float(W1 & 0xffff0000u);
            float r2l = w3 - __uint_as_float(W2 << 16);
            uint32_t L0 = pkbf2(r0l, r0h), L1 = pkbf2(r1l, r1h), L2 = pkbf2(r2l, 0.f);
            if ((unsigned)j0 <= 6u)       { *(uint32_t*)(dH + j0 * 2) = W0;       *(uint32_t*)(dL + j0 * 2) = L0; }
            if ((unsigned)(j0 + 2) <= 6u) { *(uint32_t*)(dH + (j0 + 2) * 2) = W1; *(uint32_t*)(dL + (j0 + 2) * 2) = L1; }
            if (p && (unsigned)(j0 + 4) <= 6u) { *(uint32_t*)(dH + (j0 + 4) * 2) = W2; *(uint32_t*)(dL + (j0 + 4) * 2) = L2; }
        }
    } else {
        const bool dosilu = (cc < 18);
        const int i0 = (cc & 1) * 64, row = t >> 2, f0 = (t & 3) * 16;
        float vv[16];
#pragma unroll
        for (int q = 0; q < 4; ++q) {
            float4 v = *(const float4*)(sX + row * 132 + i0 + f0 + q * 4);
            vv[q * 4 + 0] = v.x; vv[q * 4 + 1] = v.y; vv[q * 4 + 2] = v.z; vv[q * 4 + 3] = v.w;
        }
        uint32_t hq[8], lq[8];
#pragma unroll
        for (int q = 0; q < 8; ++q) {
            float pa = vv[2 * q], pb = vv[2 * q + 1];
            if (dosilu) {
                pa = pa / (1.0f + __expf(-pa));
                pb = pb / (1.0f + __expf(-pb));
            }
            hq[q] = pkbf2(pa, pb);
            float ra = pa - __uint_as_float(hq[q] << 16);
            float rb = pb - __uint_as_float(hq[q] & 0xffff0000u);
            lq[q] = pkbf2(ra, rb);
        }
        char* dH = bAh + row * 144 + f0 * 2;
        char* dL = bAl + row * 144 + f0 * 2;
        *(uint4*)(dH)      = make_uint4(hq[0], hq[1], hq[2], hq[3]);
        *(uint4*)(dH + 16) = make_uint4(hq[4], hq[5], hq[6], hq[7]);
        *(uint4*)(dL)      = make_uint4(lq[0], lq[1], lq[2], lq[3]);
        *(uint4*)(dL + 16) = make_uint4(lq[4], lq[5], lq[6], lq[7]);
    }
}

__global__ __launch_bounds__(THREADS, 2)
void enc_mma_kernel(const float* __restrict__ x, const float* __restrict__ gridp,
                    float* __restrict__ zout, float* __restrict__ xlout, int N) {
    extern __shared__ char sm[];
    char*  smA = sm + OF_A;
    uint4* sB  = (uint4*)(sm + OF_B);
    float* sX  = (float*)(sm + OF_X);

    const int t = threadIdx.x, wid = t >> 5, lane = t & 31;
    const int wr = wid & 3, wc = wid >> 2;
    const int n0 = blockIdx.x * TMR;

    const float g0   = gridp[0];
    const float invh = 1.0f / (gridp[1] - gridp[0]);

    for (int p = t; p < TMR * 32; p += THREADS) {
        int row = p >> 5, c4 = (p & 31) << 2;
        int gn = n0 + row; if (gn >= N) gn = N - 1;
        *(float4*)(sX + row * 132 + c4) = *(const float4*)(x + (size_t)gn * 128 + c4);
    }

    float accz[4][4], accx[4][4];
#pragma unroll
    for (int a = 0; a < 4; a++)
#pragma unroll
        for (int b = 0; b < 4; b++) { accz[a][b] = 0.f; accx[a][b] = 0.f; }

    const int lrow = wr * 16 + (lane & 7) + ((lane >> 3) & 1) * 8;
    const uint32_t aOff = smem_u32(smA) + lrow * 144 + ((lane >> 4) * 8) * 2;

    __syncthreads();   // sX ready

    // prologue: stage B(0), prep A(0) into buf 0
#pragma unroll
    for (int q = 0; q < 4; ++q) sB[t + q * 256] = g_Bf[t + q * 256];
    prepA(0, 0, t, smA, sX, g0, invh);
    __syncthreads();

    for (int c = 0; c < NCHUNK; ++c) {
        const int cb = c & 1, nb = cb ^ 1;
        const bool more = (c + 1 < NCHUNK);
        uint4 pb[4];
        if (more) {
#pragma unroll
            for (int q = 0; q < 4; ++q) pb[q] = g_Bf[(c + 1) * 1024 + t + q * 256];
        }
        // ---- consume chunk c ----
        const uint32_t aH = aOff + cb * A_BUF;
        const uint4* sBb = sB + cb * 1024;
#pragma unroll
        for (int kt = 0; kt < 4; ++kt) {
            uint32_t ah0, ah1, ah2, ah3, al0, al1, al2, al3;
            LDM_X4(ah0, ah1, ah2, ah3, aH + kt * 32);
            LDM_X4(al0, al1, al2, al3, aH + A_HL + kt * 32);
            if (c < 18) {
#pragma unroll
                for (int nt = 0; nt < 4; ++nt) {
                    uint4 B = sBb[(kt * 8 + wc * 4 + nt) * 32 + lane];
                    MMA16816(accz[nt], ah0, ah1, ah2, ah3, B.x, B.y);
                    MMA16816(accz[nt], ah0, ah1, ah2, ah3, B.z, B.w);
                    MMA16816(accz[nt], al0, al1, al2, al3, B.x, B.y);
                }
            } else {
#pragma unroll
                for (int nt = 0; nt < 4; ++nt) {
                    uint4 B = sBb[(kt * 8 + wc * 4 + nt) * 32 + lane];
                    MMA16816(accx[nt], ah0, ah1, ah2, ah3, B.x, B.y);
                    MMA16816(accx[nt], ah0, ah1, ah2, ah3, B.z, B.w);
                    MMA16816(accx[nt], al0, al1, al2, al3, B.x, B.y);
                }
            }
        }
        // ---- produce chunk c+1 ----
        if (more) {
#pragma unroll
            for (int q = 0; q < 4; ++q) sB[nb * 1024 + t + q * 256] = pb[q];
            prepA(c + 1, nb, t, smA, sX, g0, invh);
        }
        __syncthreads();
    }

    // ---- epilogue ----
    float p0 = 0.f, p1 = 0.f;
#pragma unroll
    for (int nt = 0; nt < 4; ++nt) {
        p0 += accz[nt][0] * accz[nt][0] + accz[nt][1] * accz[nt][1];
        p1 += accz[nt][2] * accz[nt][2] + accz[nt][3] * accz[nt][3];
    }
    p0 += __shfl_xor_sync(0xffffffffu, p0, 1);
    p0 += __shfl_xor_sync(0xffffffffu, p0, 2);
    p1 += __shfl_xor_sync(0xffffffffu, p1, 1);
    p1 += __shfl_xor_sync(0xffffffffu, p1, 2);

    float* spart = sX;   // reuse: [coltile][row]
    const int r0 = wr * 16 + (lane >> 2), r1 = r0 + 8;
    if ((lane & 3) == 0) {
        spart[wc * TMR + r0] = p0;
        spart[wc * TMR + r1] = p1;
    }
    __syncthreads();

    const float fac0 = 0.8f / fmaxf(sqrtf(spart[r0] + spart[TMR + r0]), 1e-12f);
    const float fac1 = 0.8f / fmaxf(sqrtf(spart[r1] + spart[TMR + r1]), 1e-12f);
    const bool ok0 = (n0 + r0 < N), ok1 = (n0 + r1 < N);
#pragma unroll
    for (int nt = 0; nt < 4; ++nt) {
        int n = wc * 32 + nt * 8 + (lane & 3) * 2;
        if (ok0) {
            *(float2*)(zout  + (size_t)(n0 + r0) * 64 + n) = make_float2(accz[nt][0] * fac0, accz[nt][1] * fac0);
            *(float2*)(xlout + (size_t)(n0 + r0) * 64 + n) = make_float2(accx[nt][0], accx[nt][1]);
        }
        if (ok1) {
            *(float2*)(zout  + (size_t)(n0 + r1) * 64 + n) = make_float2(accz[nt][2] * fac1, accz[nt][3] * fac1);
            *(float2*)(xlout + (size_t)(n0 + r1) * 64 + n) = make_float2(accx[nt][2], accx[nt][3]);
        }
    }
}

extern "C" void kernel_launch(void* const* d_in, const int* in_sizes, int n_in,
                              void* d_out, int out_size) {
    const float* x          = (const float*)d_in[0];
    const float* W1         = (const float*)d_in[1];
    const float* grid       = (const float*)d_in[2];
    const float* coef       = (const float*)d_in[3];
    const float* scale_base = (const float*)d_in[4];
    const float* scale_sp   = (const float*)d_in[5];
    const float* mask       = (const float*)d_in[6];
    // d_in[7] = edge_index: unused by the reference

    const int N = in_sizes[0] / 128;
    float* out   = (float*)d_out;
    float* zout  = out;
    float* xlout = out + (size_t)N * 64;

    cudaFuncSetAttribute(enc_mma_kernel, cudaFuncAttributeMaxDynamicSharedMemorySize, SMEM_TOTAL);
    prepB_kernel<<<(NCHUNK * 4 * 8 * 32 + 255) / 256, 256>>>(W1, coef, scale_base, scale_sp, mask);
    enc_mma_kernel<<<(N + TMR - 1) / TMR, THREADS, SMEM_TOTAL>>>(x, grid, zout, xlout, N);
}